// round 7
// baseline (speedup 1.0000x reference)
#include <cuda_runtime.h>
#include <cuda_fp16.h>
#include <cstdint>

// QKVAttention via HMMA mma.sync. qkv [32,192,2048] fp32 -> out [32,64,2048] fp32.
// S' = (Q * 0.125*log2e)^T K fp16 HMMA, P = ex2(S'), O += P V^T fp16 HMMA.
// Row-sums computed by an extra ones-channel block in V (exact fp32 MMA accum).
// Fused per-n16-chunk S->exp->PV pipeline keeps regs <=128 => 2 CTAs/SM.

constexpr int T  = 2048;
constexpr int CH = 64;
constexpr int BM = 128;            // queries per CTA (8 warps x m16)
constexpr int BN = 128;            // keys per iteration
constexpr int NITER = T / BN;
constexpr int THREADS = 256;
constexpr int RSH = 136;           // smem row stride in halves (272 B)
constexpr int QSZ = CH * RSH * 2;          // 17408
constexpr int KSZ = CH * RSH * 2;          // 17408 per buffer
constexpr int VSZ = 80 * RSH * 2;          // 21760 per buffer (64 data + 16 ones/zero rows)
constexpr int OFF_K0 = QSZ;
constexpr int OFF_K1 = OFF_K0 + KSZ;
constexpr int OFF_V0 = OFF_K1 + KSZ;
constexpr int OFF_V1 = OFF_V0 + VSZ;
constexpr int SMEM_TOTAL = OFF_V1 + VSZ;   // 95744 B -> 2 CTAs/SM fits 228KB
constexpr float QSCALE = 0.18033688011112042f;  // 0.125 * log2(e)

__device__ __forceinline__ uint32_t s2u(const void* p) {
    uint32_t a;
    asm("{ .reg .u64 t; cvta.to.shared.u64 t, %1; cvt.u32.u64 %0, t; }" : "=r"(a) : "l"(p));
    return a;
}
__device__ __forceinline__ void ldsm4(uint32_t* r, uint32_t a) {
    asm volatile("ldmatrix.sync.aligned.m8n8.x4.shared.b16 {%0,%1,%2,%3}, [%4];"
                 : "=r"(r[0]), "=r"(r[1]), "=r"(r[2]), "=r"(r[3]) : "r"(a));
}
__device__ __forceinline__ void ldsm4t(uint32_t* r, uint32_t a) {
    asm volatile("ldmatrix.sync.aligned.m8n8.x4.trans.shared.b16 {%0,%1,%2,%3}, [%4];"
                 : "=r"(r[0]), "=r"(r[1]), "=r"(r[2]), "=r"(r[3]) : "r"(a));
}
__device__ __forceinline__ void mma16816(float* d, const uint32_t* a, const uint32_t* b) {
    asm volatile("mma.sync.aligned.m16n8k16.row.col.f32.f16.f16.f32 "
                 "{%0,%1,%2,%3}, {%4,%5,%6,%7}, {%8,%9}, {%0,%1,%2,%3};"
                 : "+f"(d[0]), "+f"(d[1]), "+f"(d[2]), "+f"(d[3])
                 : "r"(a[0]), "r"(a[1]), "r"(a[2]), "r"(a[3]), "r"(b[0]), "r"(b[1]));
}
__device__ __forceinline__ float ex2f(float x) {
    float y; asm("ex2.approx.ftz.f32 %0, %1;" : "=f"(y) : "f"(x)); return y;
}
__device__ __forceinline__ uint32_t packh2(float lo, float hi) {
    uint32_t r; asm("cvt.rn.f16x2.f32 %0, %2, %1;" : "=r"(r) : "f"(lo), "f"(hi)); return r;
}

// Load fp32 tile [64 c][128 x] (row stride T) into 8 float4 regs.
__device__ __forceinline__ void ldg8(const float* src, int col0, int tid, float4* r) {
    #pragma unroll
    for (int it = 0; it < 8; ++it) {
        int idx = tid + it * 256;
        int c = idx >> 5, n4 = idx & 31;
        r[it] = *reinterpret_cast<const float4*>(src + (size_t)c * T + col0 + n4 * 4);
    }
}
// Convert 8 float4 -> fp16, store as [c][x] halves (row stride RSH).
__device__ __forceinline__ void cvt_sts8(const float4* r, int tid, char* dst) {
    #pragma unroll
    for (int it = 0; it < 8; ++it) {
        int idx = tid + it * 256;
        int c = idx >> 5, n4 = idx & 31;
        float4 f = r[it];
        *reinterpret_cast<uint2*>(dst + (c * RSH + n4 * 4) * 2) =
            make_uint2(packh2(f.x, f.y), packh2(f.z, f.w));
    }
}

__global__ __launch_bounds__(THREADS, 2)
void attn_hmma_kernel(const float* __restrict__ qkv, float* __restrict__ out)
{
    extern __shared__ char smem[];
    const uint32_t sb = s2u(smem);
    const int tid = threadIdx.x;
    const int lane = tid & 31, w = tid >> 5;
    const int b = blockIdx.y, t0 = blockIdx.x * BM;
    const int wm = w * 16;

    const float* qb = qkv + (size_t)b * 3 * CH * T;
    const float* kb = qb + CH * T;
    const float* vb = kb + CH * T;

    // ---- prologue ----
    {
        // Q scaled -> fp16 smem
        #pragma unroll
        for (int it = 0; it < 8; ++it) {
            int idx = tid + it * 256;
            int c = idx >> 5, n4 = idx & 31;
            float4 f = *reinterpret_cast<const float4*>(qb + (size_t)c * T + t0 + n4 * 4);
            *reinterpret_cast<uint2*>(smem + (c * RSH + n4 * 4) * 2) =
                make_uint2(packh2(f.x * QSCALE, f.y * QSCALE),
                           packh2(f.z * QSCALE, f.w * QSCALE));
        }
        // ones/zero rows (c=64..79) of both V buffers: 1.0h at row 64, n<128
        for (int idx = tid; idx < 16 * (RSH / 2); idx += THREADS) {
            int row = idx / (RSH / 2);
            int cpos = (idx % (RSH / 2)) * 2;
            uint32_t val = 0;
            if (row == 0) {
                uint32_t v0 = (cpos < 128) ? 0x3C00u : 0u;
                uint32_t v1 = (cpos + 1 < 128) ? 0x3C00u : 0u;
                val = v0 | (v1 << 16);
            }
            reinterpret_cast<uint32_t*>(smem + OFF_V0 + 64 * RSH * 2)[idx] = val;
            reinterpret_cast<uint32_t*>(smem + OFF_V1 + 64 * RSH * 2)[idx] = val;
        }
        // K0, V0 (serialized to cap register pressure)
        float4 r[8];
        ldg8(kb, 0, tid, r);
        cvt_sts8(r, tid, smem + OFF_K0);
        ldg8(vb, 0, tid, r);
        cvt_sts8(r, tid, smem + OFF_V0);
    }
    __syncthreads();

    // ---- per-lane ldmatrix address components ----
    const int lr = lane & 7, grp = lane >> 3;
    const int ac = lr + ((grp >= 2) ? 8 : 0);            // A(Q): c row, .trans
    const int am = (grp & 1) ? 8 : 0;
    const int kc = lr + ((grp & 1) ? 8 : 0);             // B(K): c row, .trans
    const int kn = (grp >= 2) ? 8 : 0;
    const int vc = lr + ((grp >= 2) ? 8 : 0);            // B(V): c row, non-trans
    const int vn = (grp & 1) ? 8 : 0;

    // ---- preload Q A-fragments (loop invariant) ----
    uint32_t qa[4][4];
    #pragma unroll
    for (int kk = 0; kk < 4; ++kk)
        ldsm4t(qa[kk], sb + ((kk * 16 + ac) * RSH + wm + am) * 2);

    float o[8][4];
    #pragma unroll
    for (int j = 0; j < 8; ++j) { o[j][0] = o[j][1] = o[j][2] = o[j][3] = 0.f; }
    float oe[4] = {0.f, 0.f, 0.f, 0.f};   // ones-channel accumulator (row sums)

    float4 kr[8], vr[8];
    for (int i = 0; i < NITER; ++i) {
        const int cur = i & 1, nxt = cur ^ 1;
        const bool more = (i + 1 < NITER);
        const uint32_t Kb = sb + OFF_K0 + cur * KSZ;
        const uint32_t Vb = sb + OFF_V0 + cur * VSZ;

        if (more) ldg8(kb, (i + 1) * BN, tid, kr);   // hide behind first S chunks

        #pragma unroll
        for (int nn = 0; nn < 8; ++nn) {
            // ---- S chunk: m16 x n16 ----
            float s[2][4];
            s[0][0]=s[0][1]=s[0][2]=s[0][3]=0.f;
            s[1][0]=s[1][1]=s[1][2]=s[1][3]=0.f;
            #pragma unroll
            for (int kk = 0; kk < 4; ++kk) {
                uint32_t kb4[4];
                ldsm4t(kb4, Kb + ((kk * 16 + kc) * RSH + nn * 16 + kn) * 2);
                mma16816(s[0], qa[kk], kb4);
                mma16816(s[1], qa[kk], kb4 + 2);
            }
            // ---- P = ex2(S), pack to A-fragment ----
            uint32_t pa[4];
            pa[0] = packh2(ex2f(s[0][0]), ex2f(s[0][1]));
            pa[1] = packh2(ex2f(s[0][2]), ex2f(s[0][3]));
            pa[2] = packh2(ex2f(s[1][0]), ex2f(s[1][1]));
            pa[3] = packh2(ex2f(s[1][2]), ex2f(s[1][3]));
            // ---- PV chunk: O += P[:, n16] V^T[n16, :] ----
            #pragma unroll
            for (int cc = 0; cc < 4; ++cc) {
                uint32_t vb4[4];
                ldsm4(vb4, Vb + ((cc * 16 + vc) * RSH + nn * 16 + vn) * 2);
                mma16816(o[2 * cc],     pa, vb4);
                mma16816(o[2 * cc + 1], pa, vb4 + 2);
            }
            // ones-channel block (rows 64..79): row sums
            {
                uint32_t ob4[4];
                ldsm4(ob4, Vb + ((64 + vc) * RSH + nn * 16 + vn) * 2);
                mma16816(oe, pa, ob4);
            }
            // mid-loop: convert K(i+1), start V(i+1) load
            if (nn == 3 && more) {
                cvt_sts8(kr, tid, smem + OFF_K0 + nxt * KSZ);
                ldg8(vb, (i + 1) * BN, tid, vr);
            }
        }
        if (more) cvt_sts8(vr, tid, smem + OFF_V0 + nxt * VSZ);
        __syncthreads();   // publish nxt buffers; all reads of cur complete
    }

    // ---- epilogue: rowsums from ones-channel (lanes lane%4==0), normalize ----
    const float sum0 = __shfl_sync(0xffffffffu, oe[0], lane & ~3);
    const float sum1 = __shfl_sync(0xffffffffu, oe[2], lane & ~3);
    const float inv0 = 1.0f / sum0;
    const float inv1 = 1.0f / sum1;

    const int r0 = wm + (lane >> 2), r1 = r0 + 8;
    // O staged c-major: Os[c][m], stride 132 (conflict-free scalar stores).
    float* Os = reinterpret_cast<float*>(smem);   // Q+K0 regions dead (33792 B needed)
    const int cq = (lane & 3) * 2;
    #pragma unroll
    for (int j = 0; j < 8; ++j) {
        int c = 8 * j + cq;
        Os[c * 132 + r0]       = o[j][0] * inv0;
        Os[(c + 1) * 132 + r0] = o[j][1] * inv0;
        Os[c * 132 + r1]       = o[j][2] * inv1;
        Os[(c + 1) * 132 + r1] = o[j][3] * inv1;
    }
    __syncthreads();

    float* ob = out + (size_t)b * CH * T;
    #pragma unroll
    for (int it = 0; it < 8; ++it) {
        int idx = tid + it * 256;
        int c = idx >> 5, m4 = idx & 31;
        float4 v = *reinterpret_cast<float4*>(&Os[c * 132 + m4 * 4]);
        *reinterpret_cast<float4*>(ob + (size_t)c * T + t0 + m4 * 4) = v;
    }
}

extern "C" void kernel_launch(void* const* d_in, const int* in_sizes, int n_in,
                              void* d_out, int out_size)
{
    (void)in_sizes; (void)n_in; (void)out_size;
    const float* qkv = (const float*)d_in[0];
    float* out = (float*)d_out;

    cudaFuncSetAttribute(attn_hmma_kernel,
                         cudaFuncAttributeMaxDynamicSharedMemorySize, SMEM_TOTAL);
    dim3 grid(T / BM, 32);
    attn_hmma_kernel<<<grid, THREADS, SMEM_TOTAL>>>(qkv, out);
}

// round 9
// speedup vs baseline: 1.1554x; 1.1554x over previous
#include <cuda_runtime.h>
#include <cuda_fp16.h>
#include <cstdint>

// QKVAttention via HMMA mma.sync. qkv [32,192,2048] fp32 -> out [32,64,2048] fp32.
// S' = (Q * 0.125*log2e)^T K fp16 HMMA, P = ex2.f16x2(S'), O += P V^T fp16 HMMA.
// 8 warps = 4(m32) x 2(n64) split: K/V ldmatrix shared across both m16 blocks
// (halves LDS traffic vs all-m split). Warp phases staggered across n-chunks.
// Row sums via ones-matrix MMA with a constant B-fragment (exact fp32).
// Cross-n-half O reduction once in the epilogue.

constexpr int T  = 2048;
constexpr int CH = 64;
constexpr int BM = 128;            // queries per CTA
constexpr int BN = 128;            // keys per iteration
constexpr int NITER = T / BN;
constexpr int THREADS = 256;
constexpr int RSH = 136;           // smem row stride in halves (272 B)
constexpr int TSZ = CH * RSH * 2;  // 17408 B per [64][128] f16 tile
constexpr int OFF_K0 = TSZ;
constexpr int OFF_K1 = OFF_K0 + TSZ;
constexpr int OFF_V0 = OFF_K1 + TSZ;
constexpr int OFF_V1 = OFF_V0 + TSZ;
constexpr int SMEM_TOTAL = OFF_V1 + TSZ;   // 87040 B
// epilogue overlays (all K/V/Q regions dead by then)
constexpr int OFF_OS0 = 0;                 // [64 c][132 m] f32
constexpr int OFF_OS1 = 33792;
constexpr int OFF_SUM = 67584;             // sums[2][128] f32
constexpr int OFF_INV = 68608;             // inv[128] f32
constexpr float QSCALE = 0.18033688011112042f;  // 0.125 * log2(e)

__device__ __forceinline__ uint32_t s2u(const void* p) {
    uint32_t a;
    asm("{ .reg .u64 t; cvta.to.shared.u64 t, %1; cvt.u32.u64 %0, t; }" : "=r"(a) : "l"(p));
    return a;
}
__device__ __forceinline__ void ldsm4(uint32_t* r, uint32_t a) {
    asm volatile("ldmatrix.sync.aligned.m8n8.x4.shared.b16 {%0,%1,%2,%3}, [%4];"
                 : "=r"(r[0]), "=r"(r[1]), "=r"(r[2]), "=r"(r[3]) : "r"(a));
}
__device__ __forceinline__ void ldsm4t(uint32_t* r, uint32_t a) {
    asm volatile("ldmatrix.sync.aligned.m8n8.x4.trans.shared.b16 {%0,%1,%2,%3}, [%4];"
                 : "=r"(r[0]), "=r"(r[1]), "=r"(r[2]), "=r"(r[3]) : "r"(a));
}
__device__ __forceinline__ void mma16816(float* d, const uint32_t* a, const uint32_t* b) {
    asm volatile("mma.sync.aligned.m16n8k16.row.col.f32.f16.f16.f32 "
                 "{%0,%1,%2,%3}, {%4,%5,%6,%7}, {%8,%9}, {%0,%1,%2,%3};"
                 : "+f"(d[0]), "+f"(d[1]), "+f"(d[2]), "+f"(d[3])
                 : "r"(a[0]), "r"(a[1]), "r"(a[2]), "r"(a[3]), "r"(b[0]), "r"(b[1]));
}
__device__ __forceinline__ uint32_t packh2(float lo, float hi) {
    uint32_t r; asm("cvt.rn.f16x2.f32 %0, %2, %1;" : "=r"(r) : "f"(lo), "f"(hi)); return r;
}
__device__ __forceinline__ uint32_t h2ex2(uint32_t x) {
    uint32_t y; asm("ex2.approx.f16x2 %0, %1;" : "=r"(y) : "r"(x)); return y;
}

// Load fp32 tile [64 c][128 x] (row stride T) into 8 float4 regs.
__device__ __forceinline__ void ldg8(const float* src, int col0, int tid, float4* r) {
    #pragma unroll
    for (int it = 0; it < 8; ++it) {
        int idx = tid + it * 256;
        int c = idx >> 5, n4 = idx & 31;
        r[it] = *reinterpret_cast<const float4*>(src + (size_t)c * T + col0 + n4 * 4);
    }
}
// Convert 8 float4 -> fp16, store as [c][x] halves (row stride RSH).
__device__ __forceinline__ void cvt_sts8(const float4* r, int tid, char* dst) {
    #pragma unroll
    for (int it = 0; it < 8; ++it) {
        int idx = tid + it * 256;
        int c = idx >> 5, n4 = idx & 31;
        float4 f = r[it];
        *reinterpret_cast<uint2*>(dst + (c * RSH + n4 * 4) * 2) =
            make_uint2(packh2(f.x, f.y), packh2(f.z, f.w));
    }
}

__global__ __launch_bounds__(THREADS, 1)
void attn_hmma_kernel(const float* __restrict__ qkv, float* __restrict__ out)
{
    extern __shared__ char smem[];
    const uint32_t sb = s2u(smem);
    const int tid = threadIdx.x;
    const int lane = tid & 31, w = tid >> 5;
    const int b = blockIdx.y, t0 = blockIdx.x * BM;
    const int wm = (w >> 1) * 32;          // m32 block
    const int wn = (w & 1) * 64;           // n64 half
    const int stag = w & 3;                // phase stagger

    const float* qb = qkv + (size_t)b * 3 * CH * T;
    const float* kb = qb + CH * T;
    const float* vb = kb + CH * T;

    // ---- prologue: Q (scaled), K0, V0 -> smem fp16 ----
    {
        #pragma unroll
        for (int it = 0; it < 8; ++it) {
            int idx = tid + it * 256;
            int c = idx >> 5, n4 = idx & 31;
            float4 f = *reinterpret_cast<const float4*>(qb + (size_t)c * T + t0 + n4 * 4);
            *reinterpret_cast<uint2*>(smem + (c * RSH + n4 * 4) * 2) =
                make_uint2(packh2(f.x * QSCALE, f.y * QSCALE),
                           packh2(f.z * QSCALE, f.w * QSCALE));
        }
        float4 st[8];
        ldg8(kb, 0, tid, st);
        cvt_sts8(st, tid, smem + OFF_K0);
        ldg8(vb, 0, tid, st);
        cvt_sts8(st, tid, smem + OFF_V0);
    }
    __syncthreads();

    // ---- per-lane ldmatrix address components ----
    const int lr = lane & 7, grp = lane >> 3;
    const int ac = lr + ((grp >= 2) ? 8 : 0);            // A(Q): c row, .trans
    const int am = (grp & 1) ? 8 : 0;
    const int kc = lr + ((grp & 1) ? 8 : 0);             // B(K): c row, .trans
    const int kn = (grp >= 2) ? 8 : 0;
    const int vc = lr + ((grp >= 2) ? 8 : 0);            // B(V): c row, non-trans
    const int vn = (grp & 1) ? 8 : 0;

    // constant B-fragment of the ones matrix (col 0 all-ones): rowsum MMA
    uint32_t ones2[2];
    ones2[0] = ones2[1] = (lane < 4) ? 0x3C003C00u : 0u;

    // ---- preload Q A-fragments (loop invariant): 2 m-blocks x 4 k-steps ----
    uint32_t qa[2][4][4];
    #pragma unroll
    for (int mb = 0; mb < 2; ++mb)
        #pragma unroll
        for (int kk = 0; kk < 4; ++kk)
            ldsm4t(qa[mb][kk], sb + ((kk * 16 + ac) * RSH + wm + mb * 16 + am) * 2);

    float o[2][8][4];
    #pragma unroll
    for (int mb = 0; mb < 2; ++mb)
        #pragma unroll
        for (int j = 0; j < 8; ++j)
            o[mb][j][0] = o[mb][j][1] = o[mb][j][2] = o[mb][j][3] = 0.f;
    float oe[2][4] = {{0.f,0.f,0.f,0.f},{0.f,0.f,0.f,0.f}};

    float4 st[8];
    for (int i = 0; i < NITER; ++i) {
        const int cur = i & 1, nxt = cur ^ 1;
        const bool more = (i + 1 < NITER);
        const uint32_t Kb = sb + OFF_K0 + cur * TSZ;
        const uint32_t Vb = sb + OFF_V0 + cur * TSZ;

        if (more) ldg8(kb, (i + 1) * BN, tid, st);   // K(i+1) into regs

        #pragma unroll
        for (int nn = 0; nn < 4; ++nn) {
            const int nnr = (nn + stag) & 3;         // staggered chunk
            const int ncol = wn + nnr * 16;

            // ---- S chunk: m32 x n16 (K fragments shared across both m-blocks) ----
            float s[2][2][4];
            #pragma unroll
            for (int mb = 0; mb < 2; ++mb)
                #pragma unroll
                for (int h = 0; h < 2; ++h)
                    s[mb][h][0] = s[mb][h][1] = s[mb][h][2] = s[mb][h][3] = 0.f;
            #pragma unroll
            for (int kk = 0; kk < 4; ++kk) {
                uint32_t kb4[4];
                ldsm4t(kb4, Kb + ((kk * 16 + kc) * RSH + ncol + kn) * 2);
                mma16816(s[0][0], qa[0][kk], kb4);
                mma16816(s[0][1], qa[0][kk], kb4 + 2);
                mma16816(s[1][0], qa[1][kk], kb4);
                mma16816(s[1][1], qa[1][kk], kb4 + 2);
            }

            // ---- P = ex2(S) in f16x2, pack to A-fragments; rowsum via ones-MMA ----
            uint32_t pa[2][4];
            #pragma unroll
            for (int mb = 0; mb < 2; ++mb) {
                pa[mb][0] = h2ex2(packh2(s[mb][0][0], s[mb][0][1]));
                pa[mb][1] = h2ex2(packh2(s[mb][0][2], s[mb][0][3]));
                pa[mb][2] = h2ex2(packh2(s[mb][1][0], s[mb][1][1]));
                pa[mb][3] = h2ex2(packh2(s[mb][1][2], s[mb][1][3]));
                mma16816(oe[mb], pa[mb], ones2);
            }

            // ---- PV chunk: O += P[:, n16] V^T[n16, :] (V frags shared across mb) ----
            #pragma unroll
            for (int cc = 0; cc < 4; ++cc) {
                uint32_t vb4[4];
                ldsm4(vb4, Vb + ((cc * 16 + vc) * RSH + ncol + vn) * 2);
                mma16816(o[0][2 * cc],     pa[0], vb4);
                mma16816(o[0][2 * cc + 1], pa[0], vb4 + 2);
                mma16816(o[1][2 * cc],     pa[1], vb4);
                mma16816(o[1][2 * cc + 1], pa[1], vb4 + 2);
            }

            if (nn == 1 && more) {
                cvt_sts8(st, tid, smem + OFF_K0 + nxt * TSZ);   // K(i+1) -> smem
                ldg8(vb, (i + 1) * BN, tid, st);                // V(i+1) into regs
            }
        }
        if (more) cvt_sts8(st, tid, smem + OFF_V0 + nxt * TSZ);
        __syncthreads();   // publish nxt buffers; all reads of cur complete
    }

    // ---- epilogue: cross-half reduction + normalize + store ----
    {
        // partial O -> Os[wn] (c-major, stride 132, conflict-free scalar stores)
        float* Os = reinterpret_cast<float*>(smem + ((w & 1) ? OFF_OS1 : OFF_OS0));
        const int cq = 2 * (lane & 3);
        #pragma unroll
        for (int mb = 0; mb < 2; ++mb) {
            const int r0 = wm + mb * 16 + (lane >> 2), r1 = r0 + 8;
            #pragma unroll
            for (int j = 0; j < 8; ++j) {
                const int c = (j >> 1) * 16 + (j & 1) * 8 + cq;
                Os[c * 132 + r0]       = o[mb][j][0];
                Os[(c + 1) * 132 + r0] = o[mb][j][1];
                Os[c * 132 + r1]       = o[mb][j][2];
                Os[(c + 1) * 132 + r1] = o[mb][j][3];
            }
        }
        // partial row sums
        float* SU = reinterpret_cast<float*>(smem + OFF_SUM) + (w & 1) * 128;
        if ((lane & 3) == 0) {
            #pragma unroll
            for (int mb = 0; mb < 2; ++mb) {
                const int r0 = wm + mb * 16 + (lane >> 2);
                SU[r0]     = oe[mb][0];
                SU[r0 + 8] = oe[mb][2];
            }
        }
        __syncthreads();

        float* S0 = reinterpret_cast<float*>(smem + OFF_SUM);
        float* IV = reinterpret_cast<float*>(smem + OFF_INV);
        if (tid < 128) IV[tid] = 1.0f / (S0[tid] + S0[128 + tid]);
        __syncthreads();

        const float* Os0 = reinterpret_cast<const float*>(smem + OFF_OS0);
        const float* Os1 = reinterpret_cast<const float*>(smem + OFF_OS1);
        float* ob = out + (size_t)b * CH * T;
        #pragma unroll
        for (int it = 0; it < 8; ++it) {
            int idx = tid + it * 256;
            int c = idx >> 5, m4 = idx & 31;
            float4 a = *reinterpret_cast<const float4*>(&Os0[c * 132 + m4 * 4]);
            float4 d = *reinterpret_cast<const float4*>(&Os1[c * 132 + m4 * 4]);
            float4 iv = *reinterpret_cast<const float4*>(&IV[m4 * 4]);
            float4 r = make_float4((a.x + d.x) * iv.x, (a.y + d.y) * iv.y,
                                   (a.z + d.z) * iv.z, (a.w + d.w) * iv.w);
            *reinterpret_cast<float4*>(ob + (size_t)c * T + t0 + m4 * 4) = r;
        }
    }
}

extern "C" void kernel_launch(void* const* d_in, const int* in_sizes, int n_in,
                              void* d_out, int out_size)
{
    (void)in_sizes; (void)n_in; (void)out_size;
    const float* qkv = (const float*)d_in[0];
    float* out = (float*)d_out;

    cudaFuncSetAttribute(attn_hmma_kernel,
                         cudaFuncAttributeMaxDynamicSharedMemorySize, SMEM_TOTAL);
    dim3 grid(T / BM, 32);
    attn_hmma_kernel<<<grid, THREADS, SMEM_TOTAL>>>(qkv, out);
}